// round 1
// baseline (speedup 1.0000x reference)
#include <cuda_runtime.h>
#include <cuda_fp16.h>
#include <cstdint>

#define MDIM 8192
#define KDIM 4096
#define NDIM 4096
#define NMB 128   // MDIM/64 row-blocks
#define NKB 64    // KDIM/64 k-blocks

// Static device scratch (allocation-free rule): masked fp16 x, transposed fp16 W, block mask.
__device__ __half g_x[(size_t)MDIM * KDIM];      // 64 MB, row-major [M][K], masked
__device__ __half g_wt[(size_t)NDIM * KDIM];     // 32 MB, [N][K] (W^T)
__device__ unsigned char g_mask[NMB * NKB];

// ---------------------------------------------------------------------------
// Kernel 1: per-64x64-block mean(|x|) > 0.8 mask. One CTA per block.
// ---------------------------------------------------------------------------
__global__ void mask_kernel(const float* __restrict__ x) {
    int kb = blockIdx.x;   // 0..63
    int mb = blockIdx.y;   // 0..127
    int tid = threadIdx.x; // 256 threads
    int r = tid >> 2;      // row within block (0..63)
    int q = tid & 3;       // 4 threads per row, 4 float4 each
    const float4* xp = (const float4*)(x + (size_t)(mb * 64 + r) * KDIM + kb * 64);
    float s = 0.f;
#pragma unroll
    for (int i = 0; i < 4; i++) {
        float4 v = xp[q + i * 4];
        s += fabsf(v.x) + fabsf(v.y) + fabsf(v.z) + fabsf(v.w);
    }
#pragma unroll
    for (int o = 16; o; o >>= 1) s += __shfl_xor_sync(0xffffffffu, s, o);
    __shared__ float ws[8];
    if ((tid & 31) == 0) ws[tid >> 5] = s;
    __syncthreads();
    if (tid == 0) {
        float t = 0.f;
#pragma unroll
        for (int i = 0; i < 8; i++) t += ws[i];
        g_mask[mb * NKB + kb] = ((t * (1.0f / 4096.0f)) > 0.8f) ? 1 : 0;
    }
}

// ---------------------------------------------------------------------------
// Kernel 2: x -> fp16 with mask applied (inactive blocks never read by GEMM,
// so we simply skip writing them).
// ---------------------------------------------------------------------------
__global__ void xconv_kernel(const float* __restrict__ x) {
    size_t id = (size_t)blockIdx.x * blockDim.x + threadIdx.x; // one per 8 halves
    int row = (int)(id >> 9);        // KDIM/8 = 512 chunks per row
    int c8  = (int)(id & 511);
    if (!g_mask[(row >> 6) * NKB + (c8 >> 3)]) return;
    const float4* xp = (const float4*)(x + (size_t)row * KDIM + (size_t)c8 * 8);
    float4 a = xp[0], b = xp[1];
    __half2* o = (__half2*)(g_x + (size_t)row * KDIM + (size_t)c8 * 8);
    o[0] = __floats2half2_rn(a.x, a.y);
    o[1] = __floats2half2_rn(a.z, a.w);
    o[2] = __floats2half2_rn(b.x, b.y);
    o[3] = __floats2half2_rn(b.z, b.w);
}

// ---------------------------------------------------------------------------
// Kernel 3: W[K][N] fp32 -> g_wt[N][K] fp16 (32x32 smem transpose tiles).
// ---------------------------------------------------------------------------
__global__ void wconv_kernel(const float* __restrict__ w) {
    __shared__ __half s[32][33];
    int n0 = blockIdx.x * 32;
    int k0 = blockIdx.y * 32;
    int xl = threadIdx.x & 31;
    int yl = threadIdx.x >> 5; // 0..7
#pragma unroll
    for (int l = 0; l < 4; l++) {
        int k = yl + l * 8;
        s[k][xl] = __float2half_rn(w[(size_t)(k0 + k) * NDIM + n0 + xl]);
    }
    __syncthreads();
#pragma unroll
    for (int l = 0; l < 4; l++) {
        int n = yl + l * 8;
        g_wt[(size_t)(n0 + n) * KDIM + k0 + xl] = s[xl][n];
    }
}

// ---------------------------------------------------------------------------
// Kernel 4: block-sparse GEMM. CTA tile = 64(M) x 128(N), K-step 64 (= mask
// granularity). 8 warps in 2x4 layout, each warp owns 32x32 via 2x4
// m16n8k16 mma tiles. fp16 in, fp32 accumulate.
// ---------------------------------------------------------------------------
__device__ __forceinline__ void ldsm4(uint32_t* r, uint32_t addr) {
    asm volatile("ldmatrix.sync.aligned.m8n8.x4.shared.b16 {%0,%1,%2,%3}, [%4];\n"
                 : "=r"(r[0]), "=r"(r[1]), "=r"(r[2]), "=r"(r[3]) : "r"(addr));
}

__device__ __forceinline__ void mma16816(float* c, const uint32_t* a, const uint32_t* b) {
    asm volatile(
        "mma.sync.aligned.m16n8k16.row.col.f32.f16.f16.f32 "
        "{%0,%1,%2,%3}, {%4,%5,%6,%7}, {%8,%9}, {%0,%1,%2,%3};\n"
        : "+f"(c[0]), "+f"(c[1]), "+f"(c[2]), "+f"(c[3])
        : "r"(a[0]), "r"(a[1]), "r"(a[2]), "r"(a[3]), "r"(b[0]), "r"(b[1]));
}

#define SA_STRIDE 72   // 64 + 8 halves pad: 144B row pitch -> conflict-free ldmatrix
#define SB_STRIDE 72

__global__ __launch_bounds__(256, 4)
void gemm_kernel(float* __restrict__ out) {
    __shared__ __half sA[64][SA_STRIDE];
    __shared__ __half sB[128][SB_STRIDE];

    int n0 = blockIdx.x * 128;
    int mb = blockIdx.y;         // row-block, 64 rows
    int tid = threadIdx.x;
    int wid = tid >> 5, lane = tid & 31;
    int wm = (wid >> 2) * 32;    // warp M offset (0 or 32)
    int wn = (wid & 3) * 32;     // warp N offset (0,32,64,96)

    float acc[2][4][4];
#pragma unroll
    for (int i = 0; i < 2; i++)
#pragma unroll
        for (int j = 0; j < 4; j++)
#pragma unroll
            for (int c = 0; c < 4; c++) acc[i][j][c] = 0.f;

    const unsigned char* mrow = g_mask + mb * NKB;
    uint32_t sA_u = (uint32_t)__cvta_generic_to_shared(&sA[0][0]);
    uint32_t sB_u = (uint32_t)__cvta_generic_to_shared(&sB[0][0]);

    // Precompute ldmatrix lane address components.
    int a_row = ((lane >> 3) & 1) * 8 + (lane & 7);  // within 16-row A tile
    int a_col = (lane >> 4) * 8;                     // 0 or 8 (k offset)
    int b_g   = lane >> 3;                           // 0..3 matrix index
    int b_row = (b_g >> 1) * 8 + (lane & 7);         // within 16-row (n) span
    int b_col = (b_g & 1) * 8;                       // 0 or 8 (k offset)

    for (int kb = 0; kb < NKB; kb++) {
        if (!mrow[kb]) continue;

        // --- Load A tile: 64 rows x 64 halves = 512 uint4 ---
        {
            const uint4* ga = (const uint4*)(g_x + ((size_t)mb * 64) * KDIM + (size_t)kb * 64);
#pragma unroll
            for (int j = 0; j < 2; j++) {
                int idx = j * 256 + tid;          // 0..511
                int r = idx >> 3, c = idx & 7;
                uint4 v = ga[(size_t)r * 512 + c];
                *(uint4*)(&sA[r][c * 8]) = v;
            }
        }
        // --- Load B tile: 128 n-rows x 64 halves = 1024 uint4 ---
        {
            const uint4* gb = (const uint4*)(g_wt + (size_t)n0 * KDIM + (size_t)kb * 64);
#pragma unroll
            for (int j = 0; j < 4; j++) {
                int idx = j * 256 + tid;          // 0..1023
                int r = idx >> 3, c = idx & 7;
                uint4 v = gb[(size_t)r * 512 + c];
                *(uint4*)(&sB[r][c * 8]) = v;
            }
        }
        __syncthreads();

#pragma unroll
        for (int ks = 0; ks < 4; ks++) {
            int k16 = ks * 16;
            uint32_t aF[2][4];
#pragma unroll
            for (int mi = 0; mi < 2; mi++) {
                int row = wm + mi * 16 + a_row;
                uint32_t addr = sA_u + (uint32_t)((row * SA_STRIDE + k16 + a_col) * 2);
                ldsm4(aF[mi], addr);
            }
            uint32_t bF[4][2];
#pragma unroll
            for (int p = 0; p < 2; p++) {
                int row = wn + p * 16 + b_row;    // two n-tiles (8 rows each) per x4
                uint32_t addr = sB_u + (uint32_t)((row * SB_STRIDE + k16 + b_col) * 2);
                uint32_t r4[4];
                ldsm4(r4, addr);
                bF[p * 2][0] = r4[0]; bF[p * 2][1] = r4[1];
                bF[p * 2 + 1][0] = r4[2]; bF[p * 2 + 1][1] = r4[3];
            }
#pragma unroll
            for (int mi = 0; mi < 2; mi++)
#pragma unroll
                for (int nj = 0; nj < 4; nj++)
                    mma16816(acc[mi][nj], aF[mi], bF[nj]);
        }
        __syncthreads();
    }

    // --- Epilogue: fp32 store (covers entire output; inactive rows -> 0) ---
    int row_base = mb * 64 + wm + (lane >> 2);
    int col_base = n0 + wn + (lane & 3) * 2;
#pragma unroll
    for (int mi = 0; mi < 2; mi++) {
#pragma unroll
        for (int nj = 0; nj < 4; nj++) {
            int col = col_base + nj * 8;
            float2 v0 = make_float2(acc[mi][nj][0], acc[mi][nj][1]);
            float2 v1 = make_float2(acc[mi][nj][2], acc[mi][nj][3]);
            *(float2*)(out + (size_t)(row_base + mi * 16) * NDIM + col) = v0;
            *(float2*)(out + (size_t)(row_base + mi * 16 + 8) * NDIM + col) = v1;
        }
    }
}

// ---------------------------------------------------------------------------
extern "C" void kernel_launch(void* const* d_in, const int* in_sizes, int n_in,
                              void* d_out, int out_size) {
    const float* x = (const float*)d_in[0];       // [8192, 4096]
    const float* w = (const float*)d_in[1];       // [4096, 4096]
    float* out = (float*)d_out;                   // [8192, 4096]

    mask_kernel<<<dim3(NKB, NMB), 256>>>(x);
    xconv_kernel<<<(MDIM * (KDIM / 8)) / 256, 256>>>(x);
    wconv_kernel<<<dim3(NDIM / 32, KDIM / 32), 256>>>(w);
    gemm_kernel<<<dim3(NDIM / 128, NMB), 256>>>(out);
}